// round 1
// baseline (speedup 1.0000x reference)
#include <cuda_runtime.h>
#include <math.h>

#define NN   4096
#define INF  512
#define HID  8
#define OUTF 256
#define CAP  (1 << 21)   // 2M nnz capacity (expected ~168K)
#define LAMBDA_ 0.7f

// ---------------- scratch (static device globals; no allocation) -------------
__device__ int   g_row_cnt[NN];
__device__ int   g_row_ptr[NN + 1];
__device__ int   g_col[CAP];
__device__ float g_h[NN * HID];
__device__ float g_dst1[NN];
__device__ float g_p1[NN];
__device__ float g_h1[NN * HID];
__device__ float g_hp[NN];
__device__ float g_dst2[NN];
__device__ float g_p2[NN];
__device__ float g_mask[NN];
__device__ float g_y1[NN * INF];
__device__ float g_y2[NN * INF];
__device__ float g_y3[NN * INF];

__device__ __forceinline__ float elu1(float v) {
    return v > 0.0f ? v : (expf(v) - 1.0f);
}

// ---------------- CSR build --------------------------------------------------
__global__ void k_count(const float* __restrict__ adj) {
    int row = blockIdx.x;
    const float* a = adj + (size_t)row * NN;
    int c = 0;
    for (int j = threadIdx.x; j < NN; j += blockDim.x) c += (a[j] > 0.5f);
    __shared__ int s[256];
    s[threadIdx.x] = c;
    __syncthreads();
    for (int o = 128; o > 0; o >>= 1) {
        if (threadIdx.x < o) s[threadIdx.x] += s[threadIdx.x + o];
        __syncthreads();
    }
    if (threadIdx.x == 0) g_row_cnt[row] = s[0];
}

__global__ void k_scan() {            // exclusive scan of 4096 counts, 1 block x 1024
    __shared__ int warp_sums[32];
    int t = threadIdx.x, lane = t & 31, w = t >> 5;
    int base = t * 4;
    int v0 = g_row_cnt[base + 0], v1 = g_row_cnt[base + 1];
    int v2 = g_row_cnt[base + 2], v3 = g_row_cnt[base + 3];
    int tsum = v0 + v1 + v2 + v3;
    int x = tsum;
    for (int o = 1; o < 32; o <<= 1) {
        int y = __shfl_up_sync(~0u, x, o);
        if (lane >= o) x += y;
    }
    if (lane == 31) warp_sums[w] = x;
    __syncthreads();
    if (w == 0) {
        int y = warp_sums[lane];
        for (int o = 1; o < 32; o <<= 1) {
            int z = __shfl_up_sync(~0u, y, o);
            if (lane >= o) y += z;
        }
        warp_sums[lane] = y;
    }
    __syncthreads();
    int excl = x - tsum + (w > 0 ? warp_sums[w - 1] : 0);
    g_row_ptr[base + 0] = excl;
    g_row_ptr[base + 1] = excl + v0;
    g_row_ptr[base + 2] = excl + v0 + v1;
    g_row_ptr[base + 3] = excl + v0 + v1 + v2;
    if (t == 1023) g_row_ptr[NN] = excl + tsum;
}

__global__ void k_fill(const float* __restrict__ adj) {  // ordered, deterministic
    int row = blockIdx.x * (blockDim.x >> 5) + (threadIdx.x >> 5);
    if (row >= NN) return;
    int lane = threadIdx.x & 31;
    const float* a = adj + (size_t)row * NN;
    int base = g_row_ptr[row];
    for (int j0 = 0; j0 < NN; j0 += 32) {
        int j = j0 + lane;
        bool nz = a[j] > 0.5f;
        unsigned b = __ballot_sync(~0u, nz);
        if (nz) g_col[base + __popc(b & ((1u << lane) - 1))] = j;
        base += __popc(b);
    }
}

// ---------------- GAT layer 1: h = x@W1, dst = h@a1[8:] ----------------------
__global__ void k_xW1(const float* __restrict__ x, const float* __restrict__ W1,
                      const float* __restrict__ a1) {
    int row = blockIdx.x * (blockDim.x >> 5) + (threadIdx.x >> 5);
    if (row >= NN) return;
    int lane = threadIdx.x & 31;
    const float* xr = x + (size_t)row * INF;
    float acc[HID];
#pragma unroll
    for (int f = 0; f < HID; f++) acc[f] = 0.0f;
    for (int j = lane; j < INF; j += 32) {
        float xv = xr[j];
        const float* wr = W1 + j * HID;
#pragma unroll
        for (int f = 0; f < HID; f++) acc[f] += xv * wr[f];
    }
#pragma unroll
    for (int f = 0; f < HID; f++)
        for (int o = 16; o; o >>= 1) acc[f] += __shfl_xor_sync(~0u, acc[f], o);
    if (lane == 0) {
        float d = 0.0f;
#pragma unroll
        for (int f = 0; f < HID; f++) {
            g_h[row * HID + f] = acc[f];
            d += acc[f] * a1[HID + f];
        }
        g_dst1[row] = d;
    }
}

// ---------------- global softmax over N values -------------------------------
__global__ void k_softmax(int which) {   // 1 block x 1024
    const float* d = which ? g_dst2 : g_dst1;
    float* p = which ? g_p2 : g_p1;
    __shared__ float red[32];
    __shared__ float sh_m, sh_s;
    int t = threadIdx.x, lane = t & 31, w = t >> 5;
    float m = -1e30f;
    for (int i = t; i < NN; i += 1024) m = fmaxf(m, d[i]);
    for (int o = 16; o; o >>= 1) m = fmaxf(m, __shfl_xor_sync(~0u, m, o));
    if (lane == 0) red[w] = m;
    __syncthreads();
    if (t == 0) {
        float mm = -1e30f;
        for (int i = 0; i < 32; i++) mm = fmaxf(mm, red[i]);
        sh_m = mm;
    }
    __syncthreads();
    float M = sh_m, s = 0.0f;
    for (int i = t; i < NN; i += 1024) {
        float e = expf(d[i] - M);
        p[i] = e;
        s += e;
    }
    for (int o = 16; o; o >>= 1) s += __shfl_xor_sync(~0u, s, o);
    if (lane == 0) red[w] = s;
    __syncthreads();
    if (t == 0) {
        float ss = 0.0f;
        for (int i = 0; i < 32; i++) ss += red[i];
        sh_s = ss;
    }
    __syncthreads();
    float inv = 1.0f / sh_s;
    for (int i = t; i < NN; i += 1024) p[i] *= inv;
}

// ---------------- sparse GAT aggregation, layer 1 (8-wide) -------------------
__global__ void k_agg1() {
    int row = blockIdx.x * (blockDim.x >> 5) + (threadIdx.x >> 5);
    if (row >= NN) return;
    int lane = threadIdx.x & 31;
    int s = g_row_ptr[row], e = g_row_ptr[row + 1];
    float acc[HID];
#pragma unroll
    for (int f = 0; f < HID; f++) acc[f] = 0.0f;
    for (int k = s + lane; k < e; k += 32) {
        int j = g_col[k];
        float pj = g_p1[j];
        const float* hj = g_h + j * HID;
#pragma unroll
        for (int f = 0; f < HID; f++) acc[f] += pj * hj[f];
    }
#pragma unroll
    for (int f = 0; f < HID; f++)
        for (int o = 16; o; o >>= 1) acc[f] += __shfl_xor_sync(~0u, acc[f], o);
    if (lane == 0) {
#pragma unroll
        for (int f = 0; f < HID; f++) g_h1[row * HID + f] = elu1(acc[f]);
    }
}

// ---------------- layer 2: hp = h1@W2, dst2 = hp*a2[1] -----------------------
__global__ void k_h1W2(const float* __restrict__ W2, const float* __restrict__ a2) {
    int i = blockIdx.x * blockDim.x + threadIdx.x;
    if (i >= NN) return;
    float s = 0.0f;
#pragma unroll
    for (int f = 0; f < HID; f++) s += g_h1[i * HID + f] * W2[f];
    g_hp[i] = s;
    g_dst2[i] = s * a2[1];
}

// ---------------- sparse GAT aggregation, layer 2 (scalar) + mask ------------
__global__ void k_agg2() {
    int row = blockIdx.x * (blockDim.x >> 5) + (threadIdx.x >> 5);
    if (row >= NN) return;
    int lane = threadIdx.x & 31;
    int s = g_row_ptr[row], e = g_row_ptr[row + 1];
    float acc = 0.0f;
    for (int k = s + lane; k < e; k += 32) {
        int j = g_col[k];
        acc += g_p2[j] * g_hp[j];
    }
    for (int o = 16; o; o >>= 1) acc += __shfl_xor_sync(~0u, acc, o);
    if (lane == 0) {
        float sc = elu1(acc);
        g_mask[row] = sc > LAMBDA_ ? 1.0f : 0.0f;
    }
}

// ---------------- SpMM: Y[row,:] = sum_{j in nbr(row)} X[j,:]  (512-wide) ----
__global__ void k_spmm(const float4* __restrict__ X, float4* __restrict__ Y) {
    int row = blockIdx.x;
    int t = threadIdx.x;                 // 128 threads = 128 float4 = 512 floats
    int s = g_row_ptr[row], e = g_row_ptr[row + 1];
    float4 acc = make_float4(0.f, 0.f, 0.f, 0.f);
    int k = s;
    for (; k + 3 < e; k += 4) {
        int j0 = g_col[k], j1 = g_col[k + 1], j2 = g_col[k + 2], j3 = g_col[k + 3];
        float4 v0 = X[(size_t)j0 * 128 + t];
        float4 v1 = X[(size_t)j1 * 128 + t];
        float4 v2 = X[(size_t)j2 * 128 + t];
        float4 v3 = X[(size_t)j3 * 128 + t];
        acc.x += v0.x + v1.x + v2.x + v3.x;
        acc.y += v0.y + v1.y + v2.y + v3.y;
        acc.z += v0.z + v1.z + v2.z + v3.z;
        acc.w += v0.w + v1.w + v2.w + v3.w;
    }
    for (; k < e; k++) {
        int j = g_col[k];
        float4 v = X[(size_t)j * 128 + t];
        acc.x += v.x; acc.y += v.y; acc.z += v.z; acc.w += v.w;
    }
    Y[(size_t)row * 128 + t] = acc;
}

// ---------------- final fused GEMM: out = [m.y1 | (1-m).y3] @ [Wa;Wc] + b ----
#define BM 128
#define BN 64
#define BK 16
__global__ void k_final(const float* __restrict__ Wsgc, const float* __restrict__ bsgc,
                        float* __restrict__ out) {
    __shared__ float As[BK][BM + 1];
    __shared__ float Bs[BK][BN];
    int bm = blockIdx.x * BM;
    int bn = blockIdx.y * BN;
    int t = threadIdx.x;                 // 256
    int ty = t >> 4, tx = t & 15;        // ty: 16 row-groups of 8, tx: 16 col-groups of 4
    float c[8][4];
#pragma unroll
    for (int i = 0; i < 8; i++)
#pragma unroll
        for (int j = 0; j < 4; j++) c[i][j] = 0.0f;

    for (int kb = 0; kb < 64; kb++) {
        bool first = kb < 32;
        const float* src = first ? g_y1 : g_y3;
        int koff = first ? kb * BK : (kb - 32) * BK;
        int wrow = first ? kb * BK : kb * BK + 512;   // skip middle 512 rows of W_sgc
        // load A tile: 2048 elems, 8/thread
#pragma unroll
        for (int q = 0; q < 8; q++) {
            int idx = t + q * 256;
            int ii = idx >> 4, kk = idx & 15;
            float msk = g_mask[bm + ii];
            float sc = first ? msk : 1.0f - msk;
            As[kk][ii] = sc * src[(size_t)(bm + ii) * INF + koff + kk];
        }
        // load B tile: 1024 elems, 4/thread
#pragma unroll
        for (int q = 0; q < 4; q++) {
            int idx = t + q * 256;
            int kk = idx >> 6, nn = idx & 63;
            Bs[kk][nn] = Wsgc[(size_t)(wrow + kk) * OUTF + bn + nn];
        }
        __syncthreads();
#pragma unroll
        for (int kk = 0; kk < BK; kk++) {
            float a[8], b[4];
#pragma unroll
            for (int i = 0; i < 8; i++) a[i] = As[kk][ty * 8 + i];
#pragma unroll
            for (int j = 0; j < 4; j++) b[j] = Bs[kk][tx * 4 + j];
#pragma unroll
            for (int i = 0; i < 8; i++)
#pragma unroll
                for (int j = 0; j < 4; j++) c[i][j] += a[i] * b[j];
        }
        __syncthreads();
    }
#pragma unroll
    for (int i = 0; i < 8; i++) {
        int row = bm + ty * 8 + i;
#pragma unroll
        for (int j = 0; j < 4; j++) {
            int col = bn + tx * 4 + j;
            out[(size_t)row * OUTF + col] = c[i][j] + bsgc[col];
        }
    }
}

// ---------------- launch -----------------------------------------------------
extern "C" void kernel_launch(void* const* d_in, const int* in_sizes, int n_in,
                              void* d_out, int out_size) {
    const float* x    = (const float*)d_in[0];
    const float* adj  = (const float*)d_in[1];
    const float* W1   = (const float*)d_in[2];
    const float* a1   = (const float*)d_in[3];
    const float* W2   = (const float*)d_in[4];
    const float* a2   = (const float*)d_in[5];
    const float* Wsgc = (const float*)d_in[6];
    const float* bsgc = (const float*)d_in[7];
    float* out = (float*)d_out;

    float4* y1; float4* y2; float4* y3;
    cudaGetSymbolAddress((void**)&y1, g_y1);
    cudaGetSymbolAddress((void**)&y2, g_y2);
    cudaGetSymbolAddress((void**)&y3, g_y3);

    // CSR build
    k_count<<<NN, 256>>>(adj);
    k_scan<<<1, 1024>>>();
    k_fill<<<NN / 8, 256>>>(adj);

    // GAT layer 1 (softmax cancellation: single global p vector)
    k_xW1<<<NN / 8, 256>>>(x, W1, a1);
    k_softmax<<<1, 1024>>>(0);
    k_agg1<<<NN / 8, 256>>>();

    // GAT layer 2 -> node scores -> binary row mask
    k_h1W2<<<NN / 256, 256>>>(W2, a2);
    k_softmax<<<1, 1024>>>(1);
    k_agg2<<<NN / 8, 256>>>();

    // K-hop aggregations (adj^2 term provably zero; only hop 1 and hop 3 survive)
    k_spmm<<<NN, 128>>>((const float4*)x, y1);
    k_spmm<<<NN, 128>>>((const float4*)y1, y2);
    k_spmm<<<NN, 128>>>((const float4*)y2, y3);

    // out = (m .* y1) @ Wsgc[0:512] + ((1-m) .* y3) @ Wsgc[1024:1536] + b
    k_final<<<dim3(NN / BM, OUTF / BN), 256>>>(Wsgc, bsgc, out);
}

// round 3
// speedup vs baseline: 1.9231x; 1.9231x over previous
#include <cuda_runtime.h>
#include <cuda_bf16.h>
#include <math.h>
#include <stdint.h>

#define NN     4096
#define INF    512
#define HID    8
#define OUTF   256
#define DEGMAX 128
#define LAMBDA_ 0.7f

// ---------------- scratch (static device globals; no allocation) -------------
__device__ int   g_deg[NN];
__device__ int   g_col[NN * DEGMAX];
__device__ __nv_bfloat16 g_xc[NN * 1536];     // [x_hi | x_lo | x_hi]
__device__ __nv_bfloat16 g_bp[512 * 1536];    // B'[n][k]: n<256 -> Wa col, n>=256 -> Wc col
__device__ float g_z0[NN * 512];              // [u = x@Wa | v = x@Wc]
__device__ float g_y1u[NN * 256];
__device__ float g_y1v[NN * 256];
__device__ float g_y2[NN * 256];
__device__ float g_y3[NN * 256];
__device__ float g_h[NN * HID];
__device__ float g_dst1[NN];
__device__ float g_p1[NN];
__device__ float g_h1[NN * HID];
__device__ float g_hp[NN];
__device__ float g_dst2[NN];
__device__ float g_p2[NN];
__device__ float g_mask[NN];
__device__ int   g_need2[NN];
__device__ int   g_list[NN];
__device__ int   g_n0;

__device__ __forceinline__ float elu1(float v) {
    return v > 0.0f ? v : (expf(v) - 1.0f);
}

// =================== conversion kernels ======================================
__global__ void k_conv_x(const float* __restrict__ x) {
    int idx = blockIdx.x * 256 + threadIdx.x;       // over 4096*128 float4
    int m = idx >> 7, c4 = idx & 127;
    float4 v = ((const float4*)x)[idx];
    __nv_bfloat16 h0 = __float2bfloat16(v.x), h1 = __float2bfloat16(v.y);
    __nv_bfloat16 h2 = __float2bfloat16(v.z), h3 = __float2bfloat16(v.w);
    __nv_bfloat16 l0 = __float2bfloat16(v.x - __bfloat162float(h0));
    __nv_bfloat16 l1 = __float2bfloat16(v.y - __bfloat162float(h1));
    __nv_bfloat16 l2 = __float2bfloat16(v.z - __bfloat162float(h2));
    __nv_bfloat16 l3 = __float2bfloat16(v.w - __bfloat162float(h3));
    __nv_bfloat162 hA, hB, lA, lB;
    hA.x = h0; hA.y = h1; hB.x = h2; hB.y = h3;
    lA.x = l0; lA.y = l1; lB.x = l2; lB.y = l3;
    __nv_bfloat162* dst = (__nv_bfloat162*)(g_xc + (size_t)m * 1536 + c4 * 4);
    dst[0] = hA; dst[1] = hB;            // seg 0: hi
    dst[256] = lA; dst[257] = lB;        // seg 1: lo (+512 elems)
    dst[512] = hA; dst[513] = hB;        // seg 2: hi (+1024 elems)
}

__global__ void k_conv_w(const float* __restrict__ Wsgc) {
    int n = blockIdx.x;                               // 512 blocks
    for (int i = 0; i < 6; i++) {
        int k = threadIdx.x + i * 256;                // 1536 k's
        int kk = k & 511, seg = k >> 9;
        float wf = (n < 256) ? Wsgc[(size_t)kk * OUTF + n]
                             : Wsgc[(size_t)(1024 + kk) * OUTF + (n - 256)];
        __nv_bfloat16 h = __float2bfloat16(wf);
        __nv_bfloat16 out = (seg == 2) ? __float2bfloat16(wf - __bfloat162float(h)) : h;
        g_bp[(size_t)n * 1536 + k] = out;
    }
}

// =================== mma.sync GEMM: Z0 = Xc @ Bp^T ===========================
// M=4096, N=512, K=1536 bf16, fp32 accum via mma.sync.m16n8k16 (baseline PTX).
// CTA tile 128x128, BK=32, 8 warps of 64(M)x32(N), double-buffered smem.
#define GBM 128
#define GBN 128
#define GBK 32

__device__ __forceinline__ uint32_t smem_u32(const void* p) {
    uint32_t a;
    asm("{ .reg .u64 t; cvta.to.shared.u64 t, %1; cvt.u32.u64 %0, t; }"
        : "=r"(a) : "l"(p));
    return a;
}
__device__ __forceinline__ void ldmx4(uint32_t* r, uint32_t addr) {
    asm volatile("ldmatrix.sync.aligned.m8n8.x4.shared.b16 {%0,%1,%2,%3}, [%4];"
                 : "=r"(r[0]), "=r"(r[1]), "=r"(r[2]), "=r"(r[3]) : "r"(addr));
}
__device__ __forceinline__ void mma16816(float* d, const uint32_t* a, const uint32_t* b) {
    asm volatile(
        "mma.sync.aligned.m16n8k16.row.col.f32.bf16.bf16.f32 "
        "{%0,%1,%2,%3}, {%4,%5,%6,%7}, {%8,%9}, {%0,%1,%2,%3};"
        : "+f"(d[0]), "+f"(d[1]), "+f"(d[2]), "+f"(d[3])
        : "r"(a[0]), "r"(a[1]), "r"(a[2]), "r"(a[3]), "r"(b[0]), "r"(b[1]));
}

__global__ void __launch_bounds__(256, 1) k_gemm() {
    // [m][4 chunks of 16B] per row (BK=32 halves = 64B), chunk-swizzled
    __shared__ uint4 As[2][GBM * 4];
    __shared__ uint4 Bs[2][GBN * 4];

    int t = threadIdx.x, wid = t >> 5, lane = t & 31;
    int bm = blockIdx.x * GBM, bn = blockIdx.y * GBN;
    int wm = (wid >> 2) * 64;          // 2 warp-rows of 64
    int wn = (wid & 3) * 32;           // 4 warp-cols of 32

    const __nv_bfloat16* Ag = g_xc + (size_t)bm * 1536;
    const __nv_bfloat16* Bg = g_bp + (size_t)bn * 1536;

    // per-thread tile-load mapping: 2 uint4 each for A and B
    int la_m[2], la_c[2];
#pragma unroll
    for (int q = 0; q < 2; q++) {
        int idx = t + q * 256;
        la_m[q] = idx >> 2;
        la_c[q] = idx & 3;
    }

    float acc[4][4][4];
#pragma unroll
    for (int i = 0; i < 4; i++)
#pragma unroll
        for (int j = 0; j < 4; j++)
#pragma unroll
            for (int r = 0; r < 4; r++) acc[i][j][r] = 0.0f;

    // ldmatrix addresses (lane-dependent, buffer-relative element offsets)
    // A: row = (lane&15), chunk add = (lane>>4)
    int a_r = lane & 15, a_cc = lane >> 4;
    // B: row = (lane&7) + ((lane>>4)&1)*8, chunk add = (lane>>3)&1
    int b_r = (lane & 7) + ((lane >> 4) & 1) * 8, b_cc = (lane >> 3) & 1;

    uint4 ra[2], rb[2];
#pragma unroll
    for (int q = 0; q < 2; q++) {
        ra[q] = *(const uint4*)(Ag + (size_t)la_m[q] * 1536 + la_c[q] * 8);
        rb[q] = *(const uint4*)(Bg + (size_t)la_m[q] * 1536 + la_c[q] * 8);
    }
    // store tile 0 into buf 0
#pragma unroll
    for (int q = 0; q < 2; q++) {
        int m = la_m[q], c = la_c[q];
        int sw = c ^ ((m >> 1) & 3);
        As[0][m * 4 + sw] = ra[q];
        Bs[0][m * 4 + sw] = rb[q];
    }
    __syncthreads();

    for (int kc = 0; kc < 48; kc++) {
        int cur = kc & 1;
        if (kc < 47) {
#pragma unroll
            for (int q = 0; q < 2; q++) {
                size_t o = (size_t)la_m[q] * 1536 + (kc + 1) * 32 + la_c[q] * 8;
                ra[q] = *(const uint4*)(Ag + o);
                rb[q] = *(const uint4*)(Bg + o);
            }
        }
        uint32_t as_base = smem_u32(&As[cur][0]);
        uint32_t bs_base = smem_u32(&Bs[cur][0]);
#pragma unroll
        for (int kk = 0; kk < 2; kk++) {           // two k16 steps
            int c0 = kk * 2;
            uint32_t afr[4][4], bfr[2][4];
#pragma unroll
            for (int mi = 0; mi < 4; mi++) {
                int m = wm + mi * 16 + a_r;
                int c = (c0 + a_cc) ^ ((m >> 1) & 3);
                ldmx4(afr[mi], as_base + m * 64 + c * 16);
            }
#pragma unroll
            for (int nj = 0; nj < 2; nj++) {
                int n = wn + nj * 16 + b_r;
                int c = (c0 + b_cc) ^ ((n >> 1) & 3);
                ldmx4(bfr[nj], bs_base + n * 64 + c * 16);
            }
#pragma unroll
            for (int mi = 0; mi < 4; mi++) {
#pragma unroll
                for (int nj = 0; nj < 4; nj++) {
                    mma16816(acc[mi][nj], afr[mi], &bfr[nj >> 1][(nj & 1) * 2]);
                }
            }
        }
        if (kc < 47) {
#pragma unroll
            for (int q = 0; q < 2; q++) {
                int m = la_m[q], c = la_c[q];
                int sw = c ^ ((m >> 1) & 3);
                As[cur ^ 1][m * 4 + sw] = ra[q];
                Bs[cur ^ 1][m * 4 + sw] = rb[q];
            }
            __syncthreads();
        }
    }

    // epilogue: d-frag (r, c): c0,c1 at (lane>>2, (lane&3)*2), c2,c3 at row+8
#pragma unroll
    for (int mi = 0; mi < 4; mi++) {
        int r0 = bm + wm + mi * 16 + (lane >> 2);
#pragma unroll
        for (int nj = 0; nj < 4; nj++) {
            int c = bn + wn + nj * 8 + (lane & 3) * 2;
            *(float2*)(g_z0 + (size_t)r0 * 512 + c) =
                make_float2(acc[mi][nj][0], acc[mi][nj][1]);
            *(float2*)(g_z0 + (size_t)(r0 + 8) * 512 + c) =
                make_float2(acc[mi][nj][2], acc[mi][nj][3]);
        }
    }
}

// =================== fused one-pass padded CSR ===============================
__global__ void k_csr(const float* __restrict__ adj) {
    int row = blockIdx.x * 8 + (threadIdx.x >> 5);
    int lane = threadIdx.x & 31;
    const float* a = adj + (size_t)row * NN;
    int base = row * DEGMAX, cnt = 0;
    for (int j0 = 0; j0 < NN; j0 += 32) {
        bool nz = a[j0 + lane] > 0.5f;
        unsigned b = __ballot_sync(~0u, nz);
        if (nz) g_col[base + cnt + __popc(b & ((1u << lane) - 1))] = j0 + lane;
        cnt += __popc(b);
    }
    if (lane == 0) g_deg[row] = cnt;
}

// =================== GAT layer 1: h = x@W1, dst = h@a1[8:] ===================
__global__ void k_xW1(const float* __restrict__ x, const float* __restrict__ W1,
                      const float* __restrict__ a1) {
    __shared__ float w1t[HID][INF];
    int t = threadIdx.x;
    for (int idx = t; idx < INF * HID; idx += 256) {
        int j = idx >> 3, f = idx & 7;
        w1t[f][j] = W1[idx];
    }
    __syncthreads();
    int row = blockIdx.x * 8 + (t >> 5);
    int lane = t & 31;
    const float* xr = x + (size_t)row * INF;
    float acc[HID];
#pragma unroll
    for (int f = 0; f < HID; f++) acc[f] = 0.0f;
    for (int it = 0; it < 16; it++) {
        int j = lane + it * 32;
        float xv = xr[j];
#pragma unroll
        for (int f = 0; f < HID; f++) acc[f] += xv * w1t[f][j];
    }
#pragma unroll
    for (int f = 0; f < HID; f++)
        for (int o = 16; o; o >>= 1) acc[f] += __shfl_xor_sync(~0u, acc[f], o);
    if (lane == 0) {
        float d = 0.0f;
#pragma unroll
        for (int f = 0; f < HID; f++) {
            g_h[row * HID + f] = acc[f];
            d += acc[f] * a1[HID + f];
        }
        g_dst1[row] = d;
    }
}

// ---------------- global softmax over N values -------------------------------
__global__ void k_softmax(int which) {
    const float* d = which ? g_dst2 : g_dst1;
    float* p = which ? g_p2 : g_p1;
    __shared__ float red[32];
    __shared__ float sh_m, sh_s;
    int t = threadIdx.x, lane = t & 31, w = t >> 5;
    float m = -1e30f;
    for (int i = t; i < NN; i += 1024) m = fmaxf(m, d[i]);
    for (int o = 16; o; o >>= 1) m = fmaxf(m, __shfl_xor_sync(~0u, m, o));
    if (lane == 0) red[w] = m;
    __syncthreads();
    if (t == 0) {
        float mm = -1e30f;
        for (int i = 0; i < 32; i++) mm = fmaxf(mm, red[i]);
        sh_m = mm;
    }
    __syncthreads();
    float M = sh_m, s = 0.0f;
    for (int i = t; i < NN; i += 1024) {
        float e = expf(d[i] - M);
        p[i] = e;
        s += e;
    }
    for (int o = 16; o; o >>= 1) s += __shfl_xor_sync(~0u, s, o);
    if (lane == 0) red[w] = s;
    __syncthreads();
    if (t == 0) {
        float ss = 0.0f;
        for (int i = 0; i < 32; i++) ss += red[i];
        sh_s = ss;
    }
    __syncthreads();
    float inv = 1.0f / sh_s;
    for (int i = t; i < NN; i += 1024) p[i] *= inv;
}

// ---------------- sparse GAT aggregation, layer 1 (8-wide) -------------------
__global__ void k_agg1() {
    int row = blockIdx.x * 8 + (threadIdx.x >> 5);
    int lane = threadIdx.x & 31;
    int s = row * DEGMAX, deg = g_deg[row];
    float acc[HID];
#pragma unroll
    for (int f = 0; f < HID; f++) acc[f] = 0.0f;
    for (int k = lane; k < deg; k += 32) {
        int j = g_col[s + k];
        float pj = g_p1[j];
        const float* hj = g_h + j * HID;
#pragma unroll
        for (int f = 0; f < HID; f++) acc[f] += pj * hj[f];
    }
#pragma unroll
    for (int f = 0; f < HID; f++)
        for (int o = 16; o; o >>= 1) acc[f] += __shfl_xor_sync(~0u, acc[f], o);
    if (lane == 0) {
#pragma unroll
        for (int f = 0; f < HID; f++) g_h1[row * HID + f] = elu1(acc[f]);
    }
}

__global__ void k_h1W2(const float* __restrict__ W2, const float* __restrict__ a2) {
    int i = blockIdx.x * blockDim.x + threadIdx.x;
    if (i >= NN) return;
    float s = 0.0f;
#pragma unroll
    for (int f = 0; f < HID; f++) s += g_h1[i * HID + f] * W2[f];
    g_hp[i] = s;
    g_dst2[i] = s * a2[1];
}

__global__ void k_agg2() {
    int row = blockIdx.x * 8 + (threadIdx.x >> 5);
    int lane = threadIdx.x & 31;
    int s = row * DEGMAX, deg = g_deg[row];
    float acc = 0.0f;
    for (int k = lane; k < deg; k += 32) {
        int j = g_col[s + k];
        acc += g_p2[j] * g_hp[j];
    }
    for (int o = 16; o; o >>= 1) acc += __shfl_xor_sync(~0u, acc, o);
    if (lane == 0) {
        float sc = elu1(acc);
        g_mask[row] = sc > LAMBDA_ ? 1.0f : 0.0f;
    }
}

// =================== mask-driven row filtering ===============================
__global__ void k_zero() {
    int idx = blockIdx.x * 256 + threadIdx.x;
    g_need2[idx] = 0;
    if (idx == 0) g_n0 = 0;
}
__global__ void k_flags() {
    int row = blockIdx.x * 8 + (threadIdx.x >> 5);
    int lane = threadIdx.x & 31;
    if (g_mask[row] != 0.0f) return;
    if (lane == 0) {
        int slot = atomicAdd(&g_n0, 1);
        g_list[slot] = row;
    }
    int s = row * DEGMAX, deg = g_deg[row];
    for (int k = lane; k < deg; k += 32) g_need2[g_col[s + k]] = 1;
}

// =================== SpMMs ====================================================
// hop1: y1v = A@v (always), y1u = A@u (only rows with mask=1)
__global__ void k_spmm1() {
    int row = blockIdx.x;
    int t = threadIdx.x;               // 128: t<64 -> v cols, t>=64 -> u cols
    bool isU = t >= 64;
    if (isU && g_mask[row] == 0.0f) return;
    int cofs = isU ? (t - 64) : (64 + t);
    int s = row * DEGMAX, deg = g_deg[row];
    const float4* X = (const float4*)g_z0;
    float4 acc = make_float4(0.f, 0.f, 0.f, 0.f);
    int k = 0;
    for (; k + 3 < deg; k += 4) {
        int j0 = g_col[s + k], j1 = g_col[s + k + 1];
        int j2 = g_col[s + k + 2], j3 = g_col[s + k + 3];
        float4 v0 = X[(size_t)j0 * 128 + cofs];
        float4 v1 = X[(size_t)j1 * 128 + cofs];
        float4 v2 = X[(size_t)j2 * 128 + cofs];
        float4 v3 = X[(size_t)j3 * 128 + cofs];
        acc.x += v0.x + v1.x + v2.x + v3.x;
        acc.y += v0.y + v1.y + v2.y + v3.y;
        acc.z += v0.z + v1.z + v2.z + v3.z;
        acc.w += v0.w + v1.w + v2.w + v3.w;
    }
    for (; k < deg; k++) {
        int j = g_col[s + k];
        float4 v = X[(size_t)j * 128 + cofs];
        acc.x += v.x; acc.y += v.y; acc.z += v.z; acc.w += v.w;
    }
    float4* dst = isU ? (float4*)g_y1u : (float4*)g_y1v;
    int c = isU ? (t - 64) : t;
    dst[(size_t)row * 64 + c] = acc;
}

// hop2: y2 = A@y1v, only for rows that neighbor a masked-0 row
__global__ void k_spmm2() {
    int row = blockIdx.x;
    if (!g_need2[row]) return;
    int t = threadIdx.x;               // 64
    int s = row * DEGMAX, deg = g_deg[row];
    const float4* X = (const float4*)g_y1v;
    float4 acc = make_float4(0.f, 0.f, 0.f, 0.f);
    int k = 0;
    for (; k + 3 < deg; k += 4) {
        int j0 = g_col[s + k], j1 = g_col[s + k + 1];
        int j2 = g_col[s + k + 2], j3 = g_col[s + k + 3];
        float4 v0 = X[(size_t)j0 * 64 + t];
        float4 v1 = X[(size_t)j1 * 64 + t];
        float4 v2 = X[(size_t)j2 * 64 + t];
        float4 v3 = X[(size_t)j3 * 64 + t];
        acc.x += v0.x + v1.x + v2.x + v3.x;
        acc.y += v0.y + v1.y + v2.y + v3.y;
        acc.z += v0.z + v1.z + v2.z + v3.z;
        acc.w += v0.w + v1.w + v2.w + v3.w;
    }
    for (; k < deg; k++) {
        int j = g_col[s + k];
        float4 v = X[(size_t)j * 64 + t];
        acc.x += v.x; acc.y += v.y; acc.z += v.z; acc.w += v.w;
    }
    ((float4*)g_y2)[(size_t)row * 64 + t] = acc;
}

// hop3: y3 = A@y2, only masked-0 rows (compacted list)
__global__ void k_spmm3() {
    int b = blockIdx.x;
    if (b >= g_n0) return;
    int row = g_list[b];
    int t = threadIdx.x;               // 64
    int s = row * DEGMAX, deg = g_deg[row];
    const float4* X = (const float4*)g_y2;
    float4 acc = make_float4(0.f, 0.f, 0.f, 0.f);
    int k = 0;
    for (; k + 3 < deg; k += 4) {
        int j0 = g_col[s + k], j1 = g_col[s + k + 1];
        int j2 = g_col[s + k + 2], j3 = g_col[s + k + 3];
        float4 v0 = X[(size_t)j0 * 64 + t];
        float4 v1 = X[(size_t)j1 * 64 + t];
        float4 v2 = X[(size_t)j2 * 64 + t];
        float4 v3 = X[(size_t)j3 * 64 + t];
        acc.x += v0.x + v1.x + v2.x + v3.x;
        acc.y += v0.y + v1.y + v2.y + v3.y;
        acc.z += v0.z + v1.z + v2.z + v3.z;
        acc.w += v0.w + v1.w + v2.w + v3.w;
    }
    for (; k < deg; k++) {
        int j = g_col[s + k];
        float4 v = X[(size_t)j * 64 + t];
        acc.x += v.x; acc.y += v.y; acc.z += v.z; acc.w += v.w;
    }
    ((float4*)g_y3)[(size_t)row * 64 + t] = acc;
}

// =================== epilogue: select + bias =================================
__global__ void k_out(const float* __restrict__ bsgc, float* __restrict__ out) {
    int idx = blockIdx.x * 256 + threadIdx.x;   // over 4096*64 float4
    int m = idx >> 6, c4 = idx & 63;
    const float4* src = (g_mask[m] != 0.0f) ? (const float4*)g_y1u
                                            : (const float4*)g_y3;
    float4 v = src[(size_t)m * 64 + c4];
    float4 b = ((const float4*)bsgc)[c4];
    v.x += b.x; v.y += b.y; v.z += b.z; v.w += b.w;
    ((float4*)out)[idx] = v;
}

// =================== launch ==================================================
extern "C" void kernel_launch(void* const* d_in, const int* in_sizes, int n_in,
                              void* d_out, int out_size) {
    const float* x    = (const float*)d_in[0];
    const float* adj  = (const float*)d_in[1];
    const float* W1   = (const float*)d_in[2];
    const float* a1   = (const float*)d_in[3];
    const float* W2   = (const float*)d_in[4];
    const float* a2   = (const float*)d_in[5];
    const float* Wsgc = (const float*)d_in[6];
    const float* bsgc = (const float*)d_in[7];
    float* out = (float*)d_out;

    // split-bf16 conversions + mma.sync GEMM: Z0 = x @ [Wa | Wc]
    k_conv_x<<<2048, 256>>>(x);
    k_conv_w<<<512, 256>>>(Wsgc);
    k_gemm<<<dim3(32, 4), 256>>>();

    // one-pass padded CSR
    k_csr<<<512, 256>>>(adj);

    // GAT chain (softmax cancellation) -> row mask
    k_xW1<<<512, 256>>>(x, W1, a1);
    k_softmax<<<1, 1024>>>(0);
    k_agg1<<<512, 256>>>();
    k_h1W2<<<16, 256>>>(W2, a2);
    k_softmax<<<1, 1024>>>(1);
    k_agg2<<<512, 256>>>();

    // mask-driven filtering for hops 2/3
    k_zero<<<16, 256>>>();
    k_flags<<<512, 256>>>();

    // hop aggregations (adj^2 output term provably zero)
    k_spmm1<<<NN, 128>>>();
    k_spmm2<<<NN, 64>>>();
    k_spmm3<<<NN, 64>>>();

    // out = mask ? A@u : A^3@v, + bias
    k_out<<<1024, 256>>>(bsgc, out);
}

// round 6
// speedup vs baseline: 2.0787x; 1.0809x over previous
#include <cuda_runtime.h>
#include <cuda_bf16.h>
#include <math.h>
#include <stdint.h>

#define NN     4096
#define INF    512
#define HID    8
#define OUTF   256
#define DEGMAX 128
#define LAMBDA_ 0.7f

// ---------------- scratch (static device globals; no allocation) -------------
__device__ int   g_deg[NN];
__device__ int   g_col[NN * DEGMAX];
__device__ __nv_bfloat16 g_xc[NN * 1536];     // [x_hi | x_lo | x_hi]
__device__ __nv_bfloat16 g_bp[512 * 1536];    // B'[n][k]: n<256 -> Wa col, n>=256 -> Wc col
__device__ float g_z0[NN * 512];              // [u = x@Wa | v = x@Wc]
__device__ float g_y1u[NN * 256];
__device__ float g_y1v[NN * 256];
__device__ float g_y2[NN * 256];
__device__ float g_y3[NN * 256];
__device__ float g_h[NN * HID];
__device__ float g_dst1[NN];
__device__ float g_p1[NN];
__device__ float g_hp[NN];
__device__ float g_dst2[NN];
__device__ float g_p2[NN];
__device__ float g_mask[NN];
__device__ int   g_need2[NN];
__device__ int   g_list[NN];
__device__ int   g_n0;

__device__ __forceinline__ float elu1(float v) {
    return v > 0.0f ? v : (expf(v) - 1.0f);
}

// =================== merged conversion kernel ================================
// blocks [0,2048): x -> split-bf16 [x_hi | x_lo | x_hi]
// blocks [2048,2560): Wsgc -> B'[n][k] (hi for segs 0/1, lo for seg 2)
__global__ void k_conv(const float* __restrict__ x, const float* __restrict__ Wsgc) {
    if (blockIdx.x < 2048) {
        int idx = blockIdx.x * 256 + threadIdx.x;       // over 4096*128 float4
        int m = idx >> 7, c4 = idx & 127;
        float4 v = ((const float4*)x)[idx];
        __nv_bfloat16 h0 = __float2bfloat16(v.x), h1 = __float2bfloat16(v.y);
        __nv_bfloat16 h2 = __float2bfloat16(v.z), h3 = __float2bfloat16(v.w);
        __nv_bfloat16 l0 = __float2bfloat16(v.x - __bfloat162float(h0));
        __nv_bfloat16 l1 = __float2bfloat16(v.y - __bfloat162float(h1));
        __nv_bfloat16 l2 = __float2bfloat16(v.z - __bfloat162float(h2));
        __nv_bfloat16 l3 = __float2bfloat16(v.w - __bfloat162float(h3));
        __nv_bfloat162 hA, hB, lA, lB;
        hA.x = h0; hA.y = h1; hB.x = h2; hB.y = h3;
        lA.x = l0; lA.y = l1; lB.x = l2; lB.y = l3;
        __nv_bfloat162* dst = (__nv_bfloat162*)(g_xc + (size_t)m * 1536 + c4 * 4);
        dst[0] = hA; dst[1] = hB;            // seg 0: hi
        dst[256] = lA; dst[257] = lB;        // seg 1: lo
        dst[512] = hA; dst[513] = hB;        // seg 2: hi
    } else {
        int n = blockIdx.x - 2048;
#pragma unroll
        for (int i = 0; i < 6; i++) {
            int k = threadIdx.x + i * 256;                // 1536 k's
            int kk = k & 511, seg = k >> 9;
            float wf = (n < 256) ? Wsgc[(size_t)kk * OUTF + n]
                                 : Wsgc[(size_t)(1024 + kk) * OUTF + (n - 256)];
            __nv_bfloat16 h = __float2bfloat16(wf);
            __nv_bfloat16 o = (seg == 2) ? __float2bfloat16(wf - __bfloat162float(h)) : h;
            g_bp[(size_t)n * 1536 + k] = o;
        }
    }
}

// =================== mma.sync GEMM: Z0 = Xc @ Bp^T ===========================
#define GBM 128
#define GBN 128

__device__ __forceinline__ uint32_t smem_u32(const void* p) {
    uint32_t a;
    asm("{ .reg .u64 t; cvta.to.shared.u64 t, %1; cvt.u32.u64 %0, t; }"
        : "=r"(a) : "l"(p));
    return a;
}
__device__ __forceinline__ void ldmx4(uint32_t* r, uint32_t addr) {
    asm volatile("ldmatrix.sync.aligned.m8n8.x4.shared.b16 {%0,%1,%2,%3}, [%4];"
                 : "=r"(r[0]), "=r"(r[1]), "=r"(r[2]), "=r"(r[3]) : "r"(addr));
}
__device__ __forceinline__ void mma16816(float* d, const uint32_t* a, const uint32_t* b) {
    asm volatile(
        "mma.sync.aligned.m16n8k16.row.col.f32.bf16.bf16.f32 "
        "{%0,%1,%2,%3}, {%4,%5,%6,%7}, {%8,%9}, {%0,%1,%2,%3};"
        : "+f"(d[0]), "+f"(d[1]), "+f"(d[2]), "+f"(d[3])
        : "r"(a[0]), "r"(a[1]), "r"(a[2]), "r"(a[3]), "r"(b[0]), "r"(b[1]));
}

__global__ void __launch_bounds__(256, 1) k_gemm() {
    __shared__ uint4 As[2][GBM * 4];
    __shared__ uint4 Bs[2][GBN * 4];

    int t = threadIdx.x, wid = t >> 5, lane = t & 31;
    int bm = blockIdx.x * GBM, bn = blockIdx.y * GBN;
    int wm = (wid >> 2) * 64;
    int wn = (wid & 3) * 32;

    const __nv_bfloat16* Ag = g_xc + (size_t)bm * 1536;
    const __nv_bfloat16* Bg = g_bp + (size_t)bn * 1536;

    int la_m[2], la_c[2];
#pragma unroll
    for (int q = 0; q < 2; q++) {
        int idx = t + q * 256;
        la_m[q] = idx >> 2;
        la_c[q] = idx & 3;
    }

    float acc[4][4][4];
#pragma unroll
    for (int i = 0; i < 4; i++)
#pragma unroll
        for (int j = 0; j < 4; j++)
#pragma unroll
            for (int r = 0; r < 4; r++) acc[i][j][r] = 0.0f;

    int a_r = lane & 15, a_cc = lane >> 4;
    int b_r = (lane & 7) + ((lane >> 4) & 1) * 8, b_cc = (lane >> 3) & 1;

    uint4 ra[2], rb[2];
#pragma unroll
    for (int q = 0; q < 2; q++) {
        ra[q] = *(const uint4*)(Ag + (size_t)la_m[q] * 1536 + la_c[q] * 8);
        rb[q] = *(const uint4*)(Bg + (size_t)la_m[q] * 1536 + la_c[q] * 8);
    }
#pragma unroll
    for (int q = 0; q < 2; q++) {
        int m = la_m[q], c = la_c[q];
        int sw = c ^ ((m >> 1) & 3);
        As[0][m * 4 + sw] = ra[q];
        Bs[0][m * 4 + sw] = rb[q];
    }
    __syncthreads();

    for (int kc = 0; kc < 48; kc++) {
        int cur = kc & 1;
        if (kc < 47) {
#pragma unroll
            for (int q = 0; q < 2; q++) {
                size_t o = (size_t)la_m[q] * 1536 + (kc + 1) * 32 + la_c[q] * 8;
                ra[q] = *(const uint4*)(Ag + o);
                rb[q] = *(const uint4*)(Bg + o);
            }
        }
        uint32_t as_base = smem_u32(&As[cur][0]);
        uint32_t bs_base = smem_u32(&Bs[cur][0]);
#pragma unroll
        for (int kk = 0; kk < 2; kk++) {
            int c0 = kk * 2;
            uint32_t afr[4][4], bfr[2][4];
#pragma unroll
            for (int mi = 0; mi < 4; mi++) {
                int m = wm + mi * 16 + a_r;
                int c = (c0 + a_cc) ^ ((m >> 1) & 3);
                ldmx4(afr[mi], as_base + m * 64 + c * 16);
            }
#pragma unroll
            for (int nj = 0; nj < 2; nj++) {
                int n = wn + nj * 16 + b_r;
                int c = (c0 + b_cc) ^ ((n >> 1) & 3);
                ldmx4(bfr[nj], bs_base + n * 64 + c * 16);
            }
#pragma unroll
            for (int mi = 0; mi < 4; mi++) {
#pragma unroll
                for (int nj = 0; nj < 4; nj++) {
                    mma16816(acc[mi][nj], afr[mi], &bfr[nj >> 1][(nj & 1) * 2]);
                }
            }
        }
        if (kc < 47) {
#pragma unroll
            for (int q = 0; q < 2; q++) {
                int m = la_m[q], c = la_c[q];
                int sw = c ^ ((m >> 1) & 3);
                As[cur ^ 1][m * 4 + sw] = ra[q];
                Bs[cur ^ 1][m * 4 + sw] = rb[q];
            }
            __syncthreads();
        }
    }

#pragma unroll
    for (int mi = 0; mi < 4; mi++) {
        int r0 = bm + wm + mi * 16 + (lane >> 2);
#pragma unroll
        for (int nj = 0; nj < 4; nj++) {
            int c = bn + wn + nj * 8 + (lane & 3) * 2;
            *(float2*)(g_z0 + (size_t)r0 * 512 + c) =
                make_float2(acc[mi][nj][0], acc[mi][nj][1]);
            *(float2*)(g_z0 + (size_t)(r0 + 8) * 512 + c) =
                make_float2(acc[mi][nj][2], acc[mi][nj][3]);
        }
    }
}

// =================== one-pass padded CSR (float4 loads) + init ===============
__global__ void k_csr(const float* __restrict__ adj) {
    // fused init for mask-driven filtering
    if (threadIdx.x < 8) g_need2[blockIdx.x * 8 + threadIdx.x] = 0;
    if (blockIdx.x == 0 && threadIdx.x == 0) g_n0 = 0;

    int row = blockIdx.x * 8 + (threadIdx.x >> 5);
    int lane = threadIdx.x & 31;
    const float4* a = (const float4*)(adj + (size_t)row * NN);
    int base = row * DEGMAX, cnt = 0;
    unsigned below = (1u << lane) - 1u;
#pragma unroll 2
    for (int j0 = 0; j0 < 1024; j0 += 32) {       // 1024 float4 per row
        float4 v = a[j0 + lane];
        unsigned b0 = __ballot_sync(~0u, v.x > 0.5f);
        unsigned b1 = __ballot_sync(~0u, v.y > 0.5f);
        unsigned b2 = __ballot_sync(~0u, v.z > 0.5f);
        unsigned b3 = __ballot_sync(~0u, v.w > 0.5f);
        int p = base + cnt +
                __popc(b0 & below) + __popc(b1 & below) +
                __popc(b2 & below) + __popc(b3 & below);
        int col0 = (j0 + lane) * 4;
        if (v.x > 0.5f) g_col[p++] = col0 + 0;
        if (v.y > 0.5f) g_col[p++] = col0 + 1;
        if (v.z > 0.5f) g_col[p++] = col0 + 2;
        if (v.w > 0.5f) g_col[p++] = col0 + 3;
        cnt += __popc(b0) + __popc(b1) + __popc(b2) + __popc(b3);
    }
    if (lane == 0) g_deg[row] = cnt;
}

// =================== GAT layer 1: h = x@W1, dst = h@a1[8:] ===================
__global__ void k_xW1(const float* __restrict__ x, const float* __restrict__ W1,
                      const float* __restrict__ a1) {
    __shared__ float w1t[HID][INF];
    int t = threadIdx.x;
    for (int idx = t; idx < INF * HID; idx += 256) {
        int j = idx >> 3, f = idx & 7;
        w1t[f][j] = W1[idx];
    }
    __syncthreads();
    int row = blockIdx.x * 8 + (t >> 5);
    int lane = t & 31;
    const float* xr = x + (size_t)row * INF;
    float acc[HID];
#pragma unroll
    for (int f = 0; f < HID; f++) acc[f] = 0.0f;
    for (int it = 0; it < 16; it++) {
        int j = lane + it * 32;
        float xv = xr[j];
#pragma unroll
        for (int f = 0; f < HID; f++) acc[f] += xv * w1t[f][j];
    }
#pragma unroll
    for (int f = 0; f < HID; f++)
        for (int o = 16; o; o >>= 1) acc[f] += __shfl_xor_sync(~0u, acc[f], o);
    if (lane == 0) {
        float d = 0.0f;
#pragma unroll
        for (int f = 0; f < HID; f++) {
            g_h[row * HID + f] = acc[f];
            d += acc[f] * a1[HID + f];
        }
        g_dst1[row] = d;
    }
}

// ---------------- global softmax (max-free: |dst| << 80, exp safe) -----------
__global__ void k_softmax(int which) {
    const float* d = which ? g_dst2 : g_dst1;
    float* p = which ? g_p2 : g_p1;
    __shared__ float red[32];
    __shared__ float sh_s;
    int t = threadIdx.x, lane = t & 31, w = t >> 5;
    float s = 0.0f;
    float e0 = expf(d[t]),        e1 = expf(d[t + 1024]);
    float e2 = expf(d[t + 2048]), e3 = expf(d[t + 3072]);
    p[t] = e0; p[t + 1024] = e1; p[t + 2048] = e2; p[t + 3072] = e3;
    s = e0 + e1 + e2 + e3;
    for (int o = 16; o; o >>= 1) s += __shfl_xor_sync(~0u, s, o);
    if (lane == 0) red[w] = s;
    __syncthreads();
    if (t == 0) {
        float ss = 0.0f;
        for (int i = 0; i < 32; i++) ss += red[i];
        sh_s = ss;
    }
    __syncthreads();
    float inv = 1.0f / sh_s;
    p[t] *= inv; p[t + 1024] *= inv; p[t + 2048] *= inv; p[t + 3072] *= inv;
}

// ------- sparse GAT agg layer 1 (8-wide) + fused h1@W2 epilogue --------------
__global__ void k_agg1(const float* __restrict__ W2, const float* __restrict__ a2) {
    int row = blockIdx.x * 8 + (threadIdx.x >> 5);
    int lane = threadIdx.x & 31;
    int s = row * DEGMAX, deg = g_deg[row];
    float acc[HID];
#pragma unroll
    for (int f = 0; f < HID; f++) acc[f] = 0.0f;
    for (int k = lane; k < deg; k += 32) {
        int j = g_col[s + k];
        float pj = g_p1[j];
        const float* hj = g_h + j * HID;
#pragma unroll
        for (int f = 0; f < HID; f++) acc[f] += pj * hj[f];
    }
#pragma unroll
    for (int f = 0; f < HID; f++)
        for (int o = 16; o; o >>= 1) acc[f] += __shfl_xor_sync(~0u, acc[f], o);
    if (lane == 0) {
        float hp = 0.0f;
#pragma unroll
        for (int f = 0; f < HID; f++) hp += elu1(acc[f]) * W2[f];
        g_hp[row] = hp;
        g_dst2[row] = hp * a2[1];
    }
}

// ------- sparse GAT agg layer 2 (scalar) + mask + fused hop-2/3 flags --------
__global__ void k_agg2() {
    int row = blockIdx.x * 8 + (threadIdx.x >> 5);
    int lane = threadIdx.x & 31;
    int s = row * DEGMAX, deg = g_deg[row];
    float acc = 0.0f;
    for (int k = lane; k < deg; k += 32) {
        int j = g_col[s + k];
        acc += g_p2[j] * g_hp[j];
    }
    for (int o = 16; o; o >>= 1) acc += __shfl_xor_sync(~0u, acc, o);
    float mask = 0.0f;
    if (lane == 0) {
        float sc = elu1(acc);
        mask = sc > LAMBDA_ ? 1.0f : 0.0f;
        g_mask[row] = mask;
        if (mask == 0.0f) {
            int slot = atomicAdd(&g_n0, 1);
            g_list[slot] = row;
        }
    }
    mask = __shfl_sync(~0u, mask, 0);
    if (mask == 0.0f) {
        for (int k = lane; k < deg; k += 32) g_need2[g_col[s + k]] = 1;
    }
}

// =================== SpMMs ====================================================
__global__ void k_spmm1() {
    int row = blockIdx.x;
    int t = threadIdx.x;               // 128: t<64 -> v cols, t>=64 -> u cols
    bool isU = t >= 64;
    if (isU && g_mask[row] == 0.0f) return;
    int cofs = isU ? (t - 64) : (64 + t);
    int s = row * DEGMAX, deg = g_deg[row];
    const float4* X = (const float4*)g_z0;
    float4 acc = make_float4(0.f, 0.f, 0.f, 0.f);
    int k = 0;
    for (; k + 3 < deg; k += 4) {
        int j0 = g_col[s + k], j1 = g_col[s + k + 1];
        int j2 = g_col[s + k + 2], j3 = g_col[s + k + 3];
        float4 v0 = X[(size_t)j0 * 128 + cofs];
        float4 v1 = X[(size_t)j1 * 128 + cofs];
        float4 v2 = X[(size_t)j2 * 128 + cofs];
        float4 v3 = X[(size_t)j3 * 128 + cofs];
        acc.x += v0.x + v1.x + v2.x + v3.x;
        acc.y += v0.y + v1.y + v2.y + v3.y;
        acc.z += v0.z + v1.z + v2.z + v3.z;
        acc.w += v0.w + v1.w + v2.w + v3.w;
    }
    for (; k < deg; k++) {
        int j = g_col[s + k];
        float4 v = X[(size_t)j * 128 + cofs];
        acc.x += v.x; acc.y += v.y; acc.z += v.z; acc.w += v.w;
    }
    float4* dst = isU ? (float4*)g_y1u : (float4*)g_y1v;
    int c = isU ? (t - 64) : t;
    dst[(size_t)row * 64 + c] = acc;
}

__global__ void k_spmm2() {
    int row = blockIdx.x;
    if (!g_need2[row]) return;
    int t = threadIdx.x;               // 64
    int s = row * DEGMAX, deg = g_deg[row];
    const float4* X = (const float4*)g_y1v;
    float4 acc = make_float4(0.f, 0.f, 0.f, 0.f);
    int k = 0;
    for (; k + 3 < deg; k += 4) {
        int j0 = g_col[s + k], j1 = g_col[s + k + 1];
        int j2 = g_col[s + k + 2], j3 = g_col[s + k + 3];
        float4 v0 = X[(size_t)j0 * 64 + t];
        float4 v1 = X[(size_t)j1 * 64 + t];
        float4 v2 = X[(size_t)j2 * 64 + t];
        float4 v3 = X[(size_t)j3 * 64 + t];
        acc.x += v0.x + v1.x + v2.x + v3.x;
        acc.y += v0.y + v1.y + v2.y + v3.y;
        acc.z += v0.z + v1.z + v2.z + v3.z;
        acc.w += v0.w + v1.w + v2.w + v3.w;
    }
    for (; k < deg; k++) {
        int j = g_col[s + k];
        float4 v = X[(size_t)j * 64 + t];
        acc.x += v.x; acc.y += v.y; acc.z += v.z; acc.w += v.w;
    }
    ((float4*)g_y2)[(size_t)row * 64 + t] = acc;
}

__global__ void k_spmm3() {
    int b = blockIdx.x;
    if (b >= g_n0) return;
    int row = g_list[b];
    int t = threadIdx.x;               // 64
    int s = row * DEGMAX, deg = g_deg[row];
    const float4* X = (const float4*)g_y2;
    float4 acc = make_float4(0.f, 0.f, 0.f, 0.f);
    int k = 0;
    for (; k + 3 < deg; k += 4) {
        int j0 = g_col[s + k], j1 = g_col[s + k + 1];
        int j2 = g_col[s + k + 2], j3 = g_col[s + k + 3];
        float4 v0 = X[(size_t)j0 * 64 + t];
        float4 v1 = X[(size_t)j1 * 64 + t];
        float4 v2 = X[(size_t)j2 * 64 + t];
        float4 v3 = X[(size_t)j3 * 64 + t];
        acc.x += v0.x + v1.x + v2.x + v3.x;
        acc.y += v0.y + v1.y + v2.y + v3.y;
        acc.z += v0.z + v1.z + v2.z + v3.z;
        acc.w += v0.w + v1.w + v2.w + v3.w;
    }
    for (; k < deg; k++) {
        int j = g_col[s + k];
        float4 v = X[(size_t)j * 64 + t];
        acc.x += v.x; acc.y += v.y; acc.z += v.z; acc.w += v.w;
    }
    ((float4*)g_y3)[(size_t)row * 64 + t] = acc;
}

// =================== epilogue: select + bias =================================
__global__ void k_out(const float* __restrict__ bsgc, float* __restrict__ out) {
    int idx = blockIdx.x * 256 + threadIdx.x;   // over 4096*64 float4
    int m = idx >> 6, c4 = idx & 63;
    const float4* src = (g_mask[m] != 0.0f) ? (const float4*)g_y1u
                                            : (const float4*)g_y3;
    float4 v = src[(size_t)m * 64 + c4];
    float4 b = ((const float4*)bsgc)[c4];
    v.x += b.x; v.y += b.y; v.z += b.z; v.w += b.w;
    ((float4*)out)[idx] = v;
}

// =================== launch ==================================================
extern "C" void kernel_launch(void* const* d_in, const int* in_sizes, int n_in,
                              void* d_out, int out_size) {
    const float* x    = (const float*)d_in[0];
    const float* adj  = (const float*)d_in[1];
    const float* W1   = (const float*)d_in[2];
    const float* a1   = (const float*)d_in[3];
    const float* W2   = (const float*)d_in[4];
    const float* a2   = (const float*)d_in[5];
    const float* Wsgc = (const float*)d_in[6];
    const float* bsgc = (const float*)d_in[7];
    float* out = (float*)d_out;

    // split-bf16 conversions + mma.sync GEMM: Z0 = x @ [Wa | Wc]
    k_conv<<<2560, 256>>>(x, Wsgc);
    k_gemm<<<dim3(32, 4), 256>>>();

    // one-pass padded CSR (float4) + filter-state init
    k_csr<<<512, 256>>>(adj);

    // GAT chain (softmax cancellation) -> row mask (+fused flags)
    k_xW1<<<512, 256>>>(x, W1, a1);
    k_softmax<<<1, 1024>>>(0);
    k_agg1<<<512, 256>>>(W2, a2);
    k_softmax<<<1, 1024>>>(1);
    k_agg2<<<512, 256>>>();

    // hop aggregations (adj^2 output term provably zero)
    k_spmm1<<<NN, 128>>>();
    k_spmm2<<<NN, 64>>>();
    k_spmm3<<<NN, 64>>>();

    // out = mask ? A@u : A^3@v, + bias
    k_out<<<1024, 256>>>(bsgc, out);
}